// round 1
// baseline (speedup 1.0000x reference)
#include <cuda_runtime.h>
#include <math.h>

// Problem constants
#define N_ROWS 8192
#define F_IN   512
#define HID    256
#define WDIM   64

// Tiling
#define TM     64          // rows per CTA
#define KT     64          // k-tile
#define NT     256         // threads per CTA
#define GRID_F (N_ROWS / TM)   // 128 CTAs

// Shared-memory strides (floats). LDA/LDE are ≡ 4 (mod 32) -> conflict-free A reads.
#define LDA 68             // X tile stride  (KT + 4)
#define LDE 260            // enc stride     (HID + 4)
#define LDW 256            // weight tile stride

// Shared-memory layout (in floats, all float4-aligned)
#define OFF_X   0
#define SZ_X    (TM * LDA)            // 4352
#define OFF_W   (OFF_X + SZ_X)        // 4352
#define SZ_W    (KT * LDW)            // 16384
#define OFF_E   (OFF_W + SZ_W)        // 20736
#define SZ_E    (TM * LDE)            // 16640
#define OFF_B1  (OFF_E + SZ_E)        // 37376
#define OFF_B2  (OFF_B1 + HID)
#define OFF_BQ  (OFF_B2 + HID)
#define OFF_WH  (OFF_BQ + WDIM)
#define SMEM_FLOATS (OFF_WH + WDIM)   // 38016
#define SMEM_BYTES  (SMEM_FLOATS * 4) // 152064 bytes

__device__ float g_partial[GRID_F];

__global__ void __launch_bounds__(NT, 1)
fused_mlp_kernel(const float* __restrict__ X,  const float* __restrict__ W1,
                 const float* __restrict__ b1, const float* __restrict__ W2,
                 const float* __restrict__ b2, const float* __restrict__ Wq,
                 const float* __restrict__ bq, const float* __restrict__ Wh)
{
    extern __shared__ float smem[];
    float* sX  = smem + OFF_X;
    float* sW  = smem + OFF_W;
    float* sE  = smem + OFF_E;
    float* sB1 = smem + OFF_B1;
    float* sB2 = smem + OFF_B2;
    float* sBQ = smem + OFF_BQ;
    float* sWH = smem + OFF_WH;

    const int tid = threadIdx.x;
    const int tx  = tid & 15;
    const int ty  = tid >> 4;
    const int r0  = ty * 4;          // 4 rows per thread
    const int tx4 = tx * 4;          // base of 4-wide col fragments
    const int row0 = blockIdx.x * TM;

    // Stage biases / Wh
    for (int i = tid; i < HID; i += NT) { sB1[i] = b1[i]; sB2[i] = b2[i]; }
    if (tid < WDIM) { sBQ[tid] = bq[tid]; sWH[tid] = Wh[tid]; }

    float acc[4][16];
#pragma unroll
    for (int i = 0; i < 4; ++i)
#pragma unroll
        for (int j = 0; j < 16; ++j) acc[i][j] = 0.f;

    // ------------------- Layer 1: enc1 = relu(X @ W1 + b1)  [TMx512]@[512x256]
    for (int kt = 0; kt < F_IN; kt += KT) {
        __syncthreads();
        // stage X tile [TM x KT]
        for (int i = tid; i < TM * (KT / 4); i += NT) {
            int r = i >> 4, f = i & 15;
            float4 v = *(const float4*)&X[(size_t)(row0 + r) * F_IN + kt + f * 4];
            *(float4*)&sX[r * LDA + f * 4] = v;
        }
        // stage W1 tile [KT x 256]
        for (int i = tid; i < KT * (HID / 4); i += NT) {
            int r = i >> 6, f = i & 63;
            float4 v = *(const float4*)&W1[(size_t)(kt + r) * HID + f * 4];
            *(float4*)&sW[r * LDW + f * 4] = v;
        }
        __syncthreads();
#pragma unroll 4
        for (int k = 0; k < KT; ++k) {
            float aa[4];
#pragma unroll
            for (int i = 0; i < 4; ++i) aa[i] = sX[(r0 + i) * LDA + k];
#pragma unroll
            for (int f = 0; f < 4; ++f) {
                float4 b4 = *(const float4*)&sW[k * LDW + tx4 + f * 64];
                float bb[4] = {b4.x, b4.y, b4.z, b4.w};
#pragma unroll
                for (int i = 0; i < 4; ++i)
#pragma unroll
                    for (int j = 0; j < 4; ++j)
                        acc[i][f * 4 + j] = fmaf(aa[i], bb[j], acc[i][f * 4 + j]);
            }
        }
    }
    __syncthreads();
    // epilogue 1: relu + bias -> sE ; reset acc
#pragma unroll
    for (int i = 0; i < 4; ++i)
#pragma unroll
        for (int f = 0; f < 4; ++f) {
            int c = tx4 + f * 64;
            float4 v;
            v.x = fmaxf(acc[i][f * 4 + 0] + sB1[c + 0], 0.f);
            v.y = fmaxf(acc[i][f * 4 + 1] + sB1[c + 1], 0.f);
            v.z = fmaxf(acc[i][f * 4 + 2] + sB1[c + 2], 0.f);
            v.w = fmaxf(acc[i][f * 4 + 3] + sB1[c + 3], 0.f);
            *(float4*)&sE[(r0 + i) * LDE + c] = v;
            acc[i][f * 4 + 0] = 0.f; acc[i][f * 4 + 1] = 0.f;
            acc[i][f * 4 + 2] = 0.f; acc[i][f * 4 + 3] = 0.f;
        }
    __syncthreads();

    // ------------------- Layer 2: enc2 = relu(enc1 @ W2 + b2)  [TMx256]@[256x256]
    for (int kt = 0; kt < HID; kt += KT) {
        __syncthreads();
        for (int i = tid; i < KT * (HID / 4); i += NT) {
            int r = i >> 6, f = i & 63;
            float4 v = *(const float4*)&W2[(size_t)(kt + r) * HID + f * 4];
            *(float4*)&sW[r * LDW + f * 4] = v;
        }
        __syncthreads();
#pragma unroll 4
        for (int k = 0; k < KT; ++k) {
            const int kk = kt + k;
            float aa[4];
#pragma unroll
            for (int i = 0; i < 4; ++i) aa[i] = sE[(r0 + i) * LDE + kk];
#pragma unroll
            for (int f = 0; f < 4; ++f) {
                float4 b4 = *(const float4*)&sW[k * LDW + tx4 + f * 64];
                float bb[4] = {b4.x, b4.y, b4.z, b4.w};
#pragma unroll
                for (int i = 0; i < 4; ++i)
#pragma unroll
                    for (int j = 0; j < 4; ++j)
                        acc[i][f * 4 + j] = fmaf(aa[i], bb[j], acc[i][f * 4 + j]);
            }
        }
    }
    // epilogue 2: relu + bias into registers, then overwrite sE
    float e2[4][16];
#pragma unroll
    for (int i = 0; i < 4; ++i)
#pragma unroll
        for (int f = 0; f < 4; ++f) {
            int c = tx4 + f * 64;
            e2[i][f * 4 + 0] = fmaxf(acc[i][f * 4 + 0] + sB2[c + 0], 0.f);
            e2[i][f * 4 + 1] = fmaxf(acc[i][f * 4 + 1] + sB2[c + 1], 0.f);
            e2[i][f * 4 + 2] = fmaxf(acc[i][f * 4 + 2] + sB2[c + 2], 0.f);
            e2[i][f * 4 + 3] = fmaxf(acc[i][f * 4 + 3] + sB2[c + 3], 0.f);
        }
    __syncthreads();   // all reads of enc1 from sE are done
#pragma unroll
    for (int i = 0; i < 4; ++i)
#pragma unroll
        for (int f = 0; f < 4; ++f) {
            int c = tx4 + f * 64;
            float4 v = make_float4(e2[i][f * 4 + 0], e2[i][f * 4 + 1],
                                   e2[i][f * 4 + 2], e2[i][f * 4 + 3]);
            *(float4*)&sE[(r0 + i) * LDE + c] = v;
        }
    // stage full Wq [256 x 64] into sW (sW free: last read before epilogue-2 sync)
    for (int i = tid; i < HID * (WDIM / 4); i += NT) {
        int r = i >> 4, f = i & 15;
        float4 v = *(const float4*)&Wq[(size_t)r * WDIM + f * 4];
        *(float4*)&sW[r * WDIM + f * 4] = v;
    }
    __syncthreads();

    // ------------------- Layer 3: q = tanh(enc2 @ Wq + bq); partial = q . Wh
    float acc3[4][4];
#pragma unroll
    for (int i = 0; i < 4; ++i)
#pragma unroll
        for (int j = 0; j < 4; ++j) acc3[i][j] = 0.f;

#pragma unroll 4
    for (int k = 0; k < HID; ++k) {
        float aa[4];
#pragma unroll
        for (int i = 0; i < 4; ++i) aa[i] = sE[(r0 + i) * LDE + k];
        float4 b4 = *(const float4*)&sW[k * WDIM + tx4];
        float bb[4] = {b4.x, b4.y, b4.z, b4.w};
#pragma unroll
        for (int i = 0; i < 4; ++i)
#pragma unroll
            for (int j = 0; j < 4; ++j)
                acc3[i][j] = fmaf(aa[i], bb[j], acc3[i][j]);
    }

    float part = 0.f;
#pragma unroll
    for (int i = 0; i < 4; ++i)
#pragma unroll
        for (int j = 0; j < 4; ++j) {
            float q = tanhf(acc3[i][j] + sBQ[tx4 + j]);
            part = fmaf(q, sWH[tx4 + j], part);
        }

    // deterministic block reduction (reuse sX region)
    __syncthreads();
    sX[tid] = part;
    __syncthreads();
    for (int s = NT / 2; s > 0; s >>= 1) {
        if (tid < s) sX[tid] += sX[tid + s];
        __syncthreads();
    }
    if (tid == 0) g_partial[blockIdx.x] = sX[0];
}

__global__ void reduce_kernel(const float* __restrict__ bh, float* __restrict__ out)
{
    __shared__ float s[GRID_F];
    int t = threadIdx.x;
    s[t] = g_partial[t];
    __syncthreads();
    for (int st = GRID_F / 2; st > 0; st >>= 1) {
        if (t < st) s[t] += s[t + st];
        __syncthreads();
    }
    if (t == 0) out[0] = s[0] + bh[0];
}

extern "C" void kernel_launch(void* const* d_in, const int* in_sizes, int n_in,
                              void* d_out, int out_size)
{
    const float* X  = (const float*)d_in[0];
    const float* W1 = (const float*)d_in[1];
    const float* b1 = (const float*)d_in[2];
    const float* W2 = (const float*)d_in[3];
    const float* b2 = (const float*)d_in[4];
    const float* Wq = (const float*)d_in[5];
    const float* bq = (const float*)d_in[6];
    const float* Wh = (const float*)d_in[7];
    const float* bh = (const float*)d_in[8];
    float* out = (float*)d_out;

    cudaFuncSetAttribute(fused_mlp_kernel,
                         cudaFuncAttributeMaxDynamicSharedMemorySize, SMEM_BYTES);

    fused_mlp_kernel<<<GRID_F, NT, SMEM_BYTES>>>(X, W1, b1, W2, b2, Wq, bq, Wh);
    reduce_kernel<<<1, GRID_F>>>(bh, out);
}

// round 4
// speedup vs baseline: 2.1563x; 2.1563x over previous
#include <cuda_runtime.h>
#include <cuda_bf16.h>
#include <math.h>
#include <stdint.h>

// ---------------- problem constants ----------------
#define N_ROWS 8192
#define F_IN   512
#define HID    256
#define WDIM   64

#define TMROWS 64
#define GRID_F (N_ROWS / TMROWS)   // 128 CTAs
#define NT     256

// weight pair counts (uint32 = 2 bf16 along K)
#define NW1P  (HID * (F_IN / 2))   // 65536  : W1T [256][256p]
#define NW2P  (HID * (HID / 2))    // 32768  : W2T [256][128p]
#define NWQP  (WDIM * (HID / 2))   // 8192   : WqT [64][128p]
#define PREP_TOTAL (NW1P + NW2P + NWQP)          // 106496
#define PREP_GRID  (PREP_TOTAL / NT)             // 416

// ---------------- smem layout (uint32 units) ----------------
// strides chosen ≡ 4 (mod 32): fragment LDS hits 32 distinct banks
#define LDA 36    // A tiles  [64 rows][32 pairs]
#define LDB 36    // B tiles  [256 n ][32 pairs]
#define LDE 132   // enc / Wq [rows][128 pairs]

#define U_AH   0                         // sAh [64*36]   (overlays sE)
#define U_AL   2304                      // sAl
#define U_EH   0                         // sEh [64*132]
#define U_EL   8448                      // sEl
#define U_BH   16896                     // sBh [256*36]
#define U_BL   26112                     // sBl
#define U_QH   16896                     // sBqh [64*132] (overlays sB)
#define U_QL   25344                     // sBql
#define U_C    35328                     // consts: b1[256] b2[256] bq[64] wh[64]
#define SMEM_U32   35968
#define SMEM_BYTES (SMEM_U32 * 4)        // 143872

// ---------------- device globals ----------------
__device__ uint32_t g_W1Thi[NW1P];
__device__ uint32_t g_W1Tlo[NW1P];
__device__ uint32_t g_W2Thi[NW2P];
__device__ uint32_t g_W2Tlo[NW2P];
__device__ uint32_t g_WqThi[NWQP];
__device__ uint32_t g_WqTlo[NWQP];
__device__ float    g_partial[GRID_F];
__device__ unsigned g_count;

// ---------------- helpers ----------------
__device__ __forceinline__ void split2(float a, float b, uint32_t& hi, uint32_t& lo) {
    __nv_bfloat16 ha = __float2bfloat16(a), hb = __float2bfloat16(b);
    float ra = a - __bfloat162float(ha), rb = b - __bfloat162float(hb);
    __nv_bfloat16 la = __float2bfloat16(ra), lb = __float2bfloat16(rb);
    hi = (uint32_t)__bfloat16_as_ushort(ha) | ((uint32_t)__bfloat16_as_ushort(hb) << 16);
    lo = (uint32_t)__bfloat16_as_ushort(la) | ((uint32_t)__bfloat16_as_ushort(lb) << 16);
}

#define MMA_BF16(acc, a, b0, b1) \
    asm volatile("mma.sync.aligned.m16n8k16.row.col.f32.bf16.bf16.f32 " \
                 "{%0,%1,%2,%3}, {%4,%5,%6,%7}, {%8,%9}, {%0,%1,%2,%3};" \
                 : "+f"((acc)[0]), "+f"((acc)[1]), "+f"((acc)[2]), "+f"((acc)[3]) \
                 : "r"((a)[0]), "r"((a)[1]), "r"((a)[2]), "r"((a)[3]), \
                   "r"(b0), "r"(b1))

// ---------------- prep: weight split + transpose (K-major pairs) ----------------
__global__ void __launch_bounds__(NT)
prep_kernel(const float* __restrict__ W1, const float* __restrict__ W2,
            const float* __restrict__ Wq)
{
    int p = blockIdx.x * NT + threadIdx.x;
    if (p == 0) g_count = 0;
    if (p < NW1P) {
        int n = p >> 8, kk = (p & 255) * 2;
        split2(W1[kk * HID + n], W1[(kk + 1) * HID + n], g_W1Thi[p], g_W1Tlo[p]);
    } else if ((p -= NW1P) < NW2P) {
        int n = p >> 7, kk = (p & 127) * 2;
        split2(W2[kk * HID + n], W2[(kk + 1) * HID + n], g_W2Thi[p], g_W2Tlo[p]);
    } else if ((p -= NW2P) < NWQP) {
        int n = p >> 7, kk = (p & 127) * 2;
        split2(Wq[kk * WDIM + n], Wq[(kk + 1) * WDIM + n], g_WqThi[p], g_WqTlo[p]);
    }
}

// ---------------- main fused kernel ----------------
__global__ void __launch_bounds__(NT, 1)
main_kernel(const float* __restrict__ X,  const float* __restrict__ b1,
            const float* __restrict__ b2, const float* __restrict__ bq,
            const float* __restrict__ Wh, const float* __restrict__ bh,
            float* __restrict__ out)
{
    extern __shared__ uint32_t S[];
    uint32_t* sAh = S + U_AH; uint32_t* sAl = S + U_AL;
    uint32_t* sEh = S + U_EH; uint32_t* sEl = S + U_EL;
    uint32_t* sBh = S + U_BH; uint32_t* sBl = S + U_BL;
    uint32_t* sQh = S + U_QH; uint32_t* sQl = S + U_QL;
    float* sB1f = (float*)(S + U_C);
    float* sB2f = sB1f + 256;
    float* sBQf = sB2f + 256;
    float* sWHf = sBQf + 64;

    const int tid  = threadIdx.x;
    const int lane = tid & 31;
    const int warp = tid >> 5;
    const int wm   = warp & 3;          // M block (16 rows)
    const int wn   = warp >> 2;         // N block (128 cols for L1/L2, 32 for L3)
    const int g    = lane >> 2;
    const int kp   = lane & 3;
    const int row0 = blockIdx.x * TMROWS;
    const int arow = wm * 16 + g;

    // consts
    sB1f[tid] = b1[tid];
    sB2f[tid] = b2[tid];
    if (tid < WDIM) { sBQf[tid] = bq[tid]; sWHf[tid] = Wh[tid]; }

    float acc[16][4];
#pragma unroll
    for (int j = 0; j < 16; ++j)
#pragma unroll
        for (int q = 0; q < 4; ++q) acc[j][q] = 0.f;

    // ========== Layer 1: enc1_pre = X @ W1  (K=512, 8 tiles of 64) ==========
    for (int t = 0; t < 8; ++t) {
        __syncthreads();
        // stage A: X fp32 -> bf16 hi/lo pairs [64 rows][32 pairs]
        for (int i = tid; i < 512; i += NT) {
            int r = i >> 3, c = i & 7;
            const float4* xs = (const float4*)&X[(size_t)(row0 + r) * F_IN + t * 64 + c * 8];
            float4 v0 = xs[0], v1 = xs[1];
            uint4 H, L;
            split2(v0.x, v0.y, H.x, L.x);
            split2(v0.z, v0.w, H.y, L.y);
            split2(v1.x, v1.y, H.z, L.z);
            split2(v1.z, v1.w, H.w, L.w);
            *(uint4*)&sAh[r * LDA + c * 4] = H;
            *(uint4*)&sAl[r * LDA + c * 4] = L;
        }
        // stage B: W1T tile [256 n][32 pairs]
        for (int i = tid; i < 2048; i += NT) {
            int n = i >> 3, c = i & 7;
            *(uint4*)&sBh[n * LDB + c * 4] = *(const uint4*)&g_W1Thi[n * 256 + t * 32 + c * 4];
            *(uint4*)&sBl[n * LDB + c * 4] = *(const uint4*)&g_W1Tlo[n * 256 + t * 32 + c * 4];
        }
        __syncthreads();
#pragma unroll
        for (int ks = 0; ks < 4; ++ks) {
            const int kb = ks * 8 + kp;
            uint32_t ah[4], al[4];
            ah[0] = sAh[arow * LDA + kb];      ah[1] = sAh[(arow + 8) * LDA + kb];
            ah[2] = sAh[arow * LDA + kb + 4];  ah[3] = sAh[(arow + 8) * LDA + kb + 4];
            al[0] = sAl[arow * LDA + kb];      al[1] = sAl[(arow + 8) * LDA + kb];
            al[2] = sAl[arow * LDA + kb + 4];  al[3] = sAl[(arow + 8) * LDA + kb + 4];
#pragma unroll
            for (int j = 0; j < 16; ++j) {
                int bi = (wn * 128 + j * 8 + g) * LDB + kb;
                uint32_t bh0 = sBh[bi], bh1 = sBh[bi + 4];
                uint32_t bl0 = sBl[bi], bl1 = sBl[bi + 4];
                MMA_BF16(acc[j], ah, bh0, bh1);
                MMA_BF16(acc[j], ah, bl0, bl1);
                MMA_BF16(acc[j], al, bh0, bh1);
            }
        }
    }

    // epilogue 1: relu+bias, split -> sE (overlays sA; sync first)
    __syncthreads();
#pragma unroll
    for (int j = 0; j < 16; ++j) {
        int n = wn * 128 + j * 8 + 2 * kp;
        float e0 = fmaxf(acc[j][0] + sB1f[n],     0.f);
        float e1 = fmaxf(acc[j][1] + sB1f[n + 1], 0.f);
        float e2 = fmaxf(acc[j][2] + sB1f[n],     0.f);
        float e3 = fmaxf(acc[j][3] + sB1f[n + 1], 0.f);
        int p0 = arow * LDE + (n >> 1), p1 = p0 + 8 * LDE;
        split2(e0, e1, sEh[p0], sEl[p0]);
        split2(e2, e3, sEh[p1], sEl[p1]);
        acc[j][0] = 0.f; acc[j][1] = 0.f; acc[j][2] = 0.f; acc[j][3] = 0.f;
    }

    // ========== Layer 2: enc2_pre = enc1 @ W2  (K=256, 4 tiles of 64) ==========
    for (int t = 0; t < 4; ++t) {
        __syncthreads();
        for (int i = tid; i < 2048; i += NT) {
            int n = i >> 3, c = i & 7;
            *(uint4*)&sBh[n * LDB + c * 4] = *(const uint4*)&g_W2Thi[n * 128 + t * 32 + c * 4];
            *(uint4*)&sBl[n * LDB + c * 4] = *(const uint4*)&g_W2Tlo[n * 128 + t * 32 + c * 4];
        }
        __syncthreads();
#pragma unroll
        for (int ks = 0; ks < 4; ++ks) {
            const int kb  = ks * 8 + kp;         // within B tile
            const int kbE = t * 32 + kb;         // within full enc K
            uint32_t ah[4], al[4];
            ah[0] = sEh[arow * LDE + kbE];      ah[1] = sEh[(arow + 8) * LDE + kbE];
            ah[2] = sEh[arow * LDE + kbE + 4];  ah[3] = sEh[(arow + 8) * LDE + kbE + 4];
            al[0] = sEl[arow * LDE + kbE];      al[1] = sEl[(arow + 8) * LDE + kbE];
            al[2] = sEl[arow * LDE + kbE + 4];  al[3] = sEl[(arow + 8) * LDE + kbE + 4];
#pragma unroll
            for (int j = 0; j < 16; ++j) {
                int bi = (wn * 128 + j * 8 + g) * LDB + kb;
                uint32_t bh0 = sBh[bi], bh1 = sBh[bi + 4];
                uint32_t bl0 = sBl[bi], bl1 = sBl[bi + 4];
                MMA_BF16(acc[j], ah, bh0, bh1);
                MMA_BF16(acc[j], ah, bl0, bl1);
                MMA_BF16(acc[j], al, bh0, bh1);
            }
        }
    }

    // epilogue 2: relu+bias -> sE in place; stage WqT -> sQ (overlays sB)
    __syncthreads();
#pragma unroll
    for (int j = 0; j < 16; ++j) {
        int n = wn * 128 + j * 8 + 2 * kp;
        float e0 = fmaxf(acc[j][0] + sB2f[n],     0.f);
        float e1 = fmaxf(acc[j][1] + sB2f[n + 1], 0.f);
        float e2 = fmaxf(acc[j][2] + sB2f[n],     0.f);
        float e3 = fmaxf(acc[j][3] + sB2f[n + 1], 0.f);
        int p0 = arow * LDE + (n >> 1), p1 = p0 + 8 * LDE;
        split2(e0, e1, sEh[p0], sEl[p0]);
        split2(e2, e3, sEh[p1], sEl[p1]);
    }
    for (int i = tid; i < 2048; i += NT) {
        int n = i >> 5, c = i & 31;
        *(uint4*)&sQh[n * LDE + c * 4] = *(const uint4*)&g_WqThi[n * 128 + c * 4];
        *(uint4*)&sQl[n * LDE + c * 4] = *(const uint4*)&g_WqTlo[n * 128 + c * 4];
    }
    __syncthreads();

    // ========== Layer 3: q_pre = enc2 @ Wq  (K=256, N=64) ==========
    float acc3[4][4];
#pragma unroll
    for (int j = 0; j < 4; ++j)
#pragma unroll
        for (int q = 0; q < 4; ++q) acc3[j][q] = 0.f;

#pragma unroll
    for (int ks = 0; ks < 16; ++ks) {
        const int kb = ks * 8 + kp;
        uint32_t ah[4], al[4];
        ah[0] = sEh[arow * LDE + kb];      ah[1] = sEh[(arow + 8) * LDE + kb];
        ah[2] = sEh[arow * LDE + kb + 4];  ah[3] = sEh[(arow + 8) * LDE + kb + 4];
        al[0] = sEl[arow * LDE + kb];      al[1] = sEl[(arow + 8) * LDE + kb];
        al[2] = sEl[arow * LDE + kb + 4];  al[3] = sEl[(arow + 8) * LDE + kb + 4];
#pragma unroll
        for (int j = 0; j < 4; ++j) {
            int bi = (wn * 32 + j * 8 + g) * LDE + kb;
            uint32_t bh0 = sQh[bi], bh1 = sQh[bi + 4];
            uint32_t bl0 = sQl[bi], bl1 = sQl[bi + 4];
            MMA_BF16(acc3[j], ah, bh0, bh1);
            MMA_BF16(acc3[j], ah, bl0, bl1);
            MMA_BF16(acc3[j], al, bh0, bh1);
        }
    }

    // final: q = tanh(pre + bq); partial = sum q * Wh
    float part = 0.f;
#pragma unroll
    for (int j = 0; j < 4; ++j) {
        int n = wn * 32 + j * 8 + 2 * kp;
        part = fmaf(tanhf(acc3[j][0] + sBQf[n]),     sWHf[n],     part);
        part = fmaf(tanhf(acc3[j][1] + sBQf[n + 1]), sWHf[n + 1], part);
        part = fmaf(tanhf(acc3[j][2] + sBQf[n]),     sWHf[n],     part);
        part = fmaf(tanhf(acc3[j][3] + sBQf[n + 1]), sWHf[n + 1], part);
    }

    __syncthreads();
    float* red = (float*)S;
    red[tid] = part;
    __syncthreads();
    for (int s = NT / 2; s > 0; s >>= 1) {
        if (tid < s) red[tid] += red[tid + s];
        __syncthreads();
    }

    __shared__ int s_last;
    if (tid == 0) {
        g_partial[blockIdx.x] = red[0];
        __threadfence();
        unsigned v = atomicAdd(&g_count, 1u);
        s_last = (v == GRID_F - 1) ? 1 : 0;
    }
    __syncthreads();
    if (s_last && tid == 0) {
        __threadfence();
        const volatile float* gp = (const volatile float*)g_partial;
        float s = 0.f;
        for (int i = 0; i < GRID_F; ++i) s += gp[i];
        out[0] = s + bh[0];
    }
}

extern "C" void kernel_launch(void* const* d_in, const int* in_sizes, int n_in,
                              void* d_out, int out_size)
{
    const float* X  = (const float*)d_in[0];
    const float* W1 = (const float*)d_in[1];
    const float* b1 = (const float*)d_in[2];
    const float* W2 = (const float*)d_in[3];
    const float* b2 = (const float*)d_in[4];
    const float* Wq = (const float*)d_in[5];
    const float* bq = (const float*)d_in[6];
    const float* Wh = (const float*)d_in[7];
    const float* bh = (const float*)d_in[8];
    float* out = (float*)d_out;

    cudaFuncSetAttribute(main_kernel,
                         cudaFuncAttributeMaxDynamicSharedMemorySize, SMEM_BYTES);

    prep_kernel<<<PREP_GRID, NT>>>(W1, W2, Wq);
    main_kernel<<<GRID_F, NT, SMEM_BYTES>>>(X, b1, b2, bq, Wh, bh, out);
}